// round 1
// baseline (speedup 1.0000x reference)
#include <cuda_runtime.h>
#include <math.h>
#include <stdint.h>

// Problem constants
#define B_TOTAL   131072
#define DCOND     64
#define H_DIM     512
#define NOUT      513       // W2 column count (last col = unused bias)
#define NCOL      512       // used param columns = 32 d * 8 centers * 2 comps
#define D_HALVE   32
#define TWO_PI_F  6.283185307179586f

// Packed (eta-folded, stride-512, 16B-alignable) copy of W2
__device__ float g_W2p[H_DIM * NCOL];

__global__ void pack_w2_kernel(const float* __restrict__ W2,
                               const float* __restrict__ eta) {
    int i = blockIdx.x * blockDim.x + threadIdx.x;   // over 512*512
    float e = eta[0];
    int k = i >> 9;
    int c = i & 511;
    g_W2p[i] = W2[k * NOUT + c] * e;
}

// ---------------------------------------------------------------------------
// Generic double-buffered K-staged GEMM accumulate phase.
//   gsrc : [NT*8][512] fp32, row-major, 16B aligned
//   asrc : smem activations, asrc[(8*wp+i)*ASTRIDE + k]
//   stage: smem [2][8*512] staging buffers
//   acc  : 8 rows x 8 ull (=16 fp32 cols) accumulators, cols = 4*tn + 128*s
// ---------------------------------------------------------------------------
template <int NT, int ASTRIDE>
__device__ __forceinline__ void gemm_phase(const float* __restrict__ gsrc,
                                           const float* __restrict__ asrc,
                                           float* stage,
                                           unsigned long long (&acc)[8][8],
                                           int wp, int tn, int tid) {
    const float4* g4 = reinterpret_cast<const float4*>(gsrc);

    // prologue: tile 0
    float4 pre[4];
#pragma unroll
    for (int j = 0; j < 4; j++) pre[j] = g4[tid + 256 * j];
#pragma unroll
    for (int j = 0; j < 4; j++)
        reinterpret_cast<float4*>(stage)[tid + 256 * j] = pre[j];
    __syncthreads();

    for (int t = 0; t < NT; t++) {
        if (t + 1 < NT) {
#pragma unroll
            for (int j = 0; j < 4; j++)
                pre[j] = g4[(t + 1) * 1024 + tid + 256 * j];
        }
        const float* cur = stage + (t & 1) * 4096;
        const ulonglong2* bu = reinterpret_cast<const ulonglong2*>(cur);

#pragma unroll
        for (int kk = 0; kk < 8; kk++) {
            int k = t * 8 + kk;
            unsigned long long a2[8];
#pragma unroll
            for (int i = 0; i < 8; i++) {
                unsigned int au = __float_as_uint(asrc[(8 * wp + i) * ASTRIDE + k]);
                asm("mov.b64 %0, {%1, %1};" : "=l"(a2[i]) : "r"(au));
            }
            unsigned long long bv[8];
#pragma unroll
            for (int s = 0; s < 4; s++) {
                ulonglong2 bb = bu[kk * 128 + tn + 32 * s];
                bv[2 * s] = bb.x;
                bv[2 * s + 1] = bb.y;
            }
#pragma unroll
            for (int i = 0; i < 8; i++) {
#pragma unroll
                for (int j = 0; j < 8; j++) {
                    asm("fma.rn.f32x2 %0, %1, %2, %0;"
                        : "+l"(acc[i][j])
                        : "l"(a2[i]), "l"(bv[j]));
                }
            }
        }

        if (t + 1 < NT) {
            float4* st4 = reinterpret_cast<float4*>(stage + ((t + 1) & 1) * 4096);
#pragma unroll
            for (int j = 0; j < 4; j++) st4[tid + 256 * j] = pre[j];
        }
        __syncthreads();
    }
}

__device__ __forceinline__ float ull_lo(unsigned long long v) {
    return __uint_as_float((unsigned int)(v & 0xffffffffull));
}
__device__ __forceinline__ float ull_hi(unsigned long long v) {
    return __uint_as_float((unsigned int)(v >> 32));
}

// ---------------------------------------------------------------------------
// Fused kernel: 64 rows per CTA, 256 threads.
// Thread (wp = tid/32, tn = tid%32) owns rows {8*wp+i, i<8} and
// param columns {4*tn + 128*s + j, s<4, j<4}  -> d = (tn>>2)+8s,
// centers 2*(tn&3), 2*(tn&3)+1 (both components).
// ---------------------------------------------------------------------------
__global__ __launch_bounds__(256, 1)
void moebius_fused_kernel(const float* __restrict__ theta,
                          const float* __restrict__ r_in,
                          const float* __restrict__ x_cond,
                          const float* __restrict__ W1,
                          const float* __restrict__ b1,
                          const float* __restrict__ b2,
                          const float* __restrict__ eta,
                          float* __restrict__ out) {
    extern __shared__ float smem[];
    float* h_s   = smem;                     // [64][512]   128 KB
    float* x_s   = smem + 64 * 512;          // [64][64]     16 KB
    float* stage = smem + 64 * 512 + 64 * 64; // [2][8*512]  32 KB

    const int tid = threadIdx.x;
    const int wp = tid >> 5;
    const int tn = tid & 31;
    const int blockRow = blockIdx.x * 64;

    // load x tile (coalesced)
    {
        const float4* xg = reinterpret_cast<const float4*>(x_cond + blockRow * DCOND);
        float4* xs4 = reinterpret_cast<float4*>(x_s);
#pragma unroll
        for (int j = 0; j < 4; j++) xs4[tid + 256 * j] = xg[tid + 256 * j];
    }
    __syncthreads();

    unsigned long long acc[8][8];
#pragma unroll
    for (int i = 0; i < 8; i++)
#pragma unroll
        for (int j = 0; j < 8; j++) acc[i][j] = 0ull;

    // ---- phase 1: h = relu(x @ W1 + b1) ----
    gemm_phase<8, 64>(W1, x_s, stage, acc, wp, tn, tid);

    // apply bias + relu, write h to smem (conflict-free float4 pattern)
#pragma unroll
    for (int s = 0; s < 4; s++) {
        float4 bb1 = *reinterpret_cast<const float4*>(b1 + 4 * tn + 128 * s);
#pragma unroll
        for (int i = 0; i < 8; i++) {
            float v0 = fmaxf(ull_lo(acc[i][2 * s])     + bb1.x, 0.0f);
            float v1 = fmaxf(ull_hi(acc[i][2 * s])     + bb1.y, 0.0f);
            float v2 = fmaxf(ull_lo(acc[i][2 * s + 1]) + bb1.z, 0.0f);
            float v3 = fmaxf(ull_hi(acc[i][2 * s + 1]) + bb1.w, 0.0f);
            float4* dst = reinterpret_cast<float4*>(
                h_s + (8 * wp + i) * 512 + 4 * tn + 128 * s);
            *dst = make_float4(v0, v1, v2, v3);
        }
    }
    // zero accumulators for phase 2 (gemm_phase prologue's barrier orders
    // the h_s writes above against other threads' reads)
#pragma unroll
    for (int i = 0; i < 8; i++)
#pragma unroll
        for (int j = 0; j < 8; j++) acc[i][j] = 0ull;

    // ---- phase 2: params = h @ (W2*eta) ----
    gemm_phase<64, 512>(g_W2p, h_s, stage, acc, wp, tn, tid);

    // ---- epilogue: Moebius map + angle mean + log-det ----
    const float e = eta[0];
    float4 b2v[4];
#pragma unroll
    for (int s = 0; s < 4; s++) {
        float4 bb = *reinterpret_cast<const float4*>(b2 + 4 * tn + 128 * s);
        b2v[s] = make_float4(bb.x * e, bb.y * e, bb.z * e, bb.w * e);
    }
    const int q = tn >> 2;     // d = 8*s + q
    const int pgrp = tn & 3;   // 4-lane center group

#pragma unroll
    for (int i = 0; i < 8; i++) {
        const int grow = blockRow + 8 * wp + i;
#pragma unroll
        for (int s = 0; s < 4; s++) {
            const int d = 8 * s + q;
            const float th = theta[grow * D_HALVE + d];
            const float rr = r_in[grow * D_HALVE + d];
            float sn, cs;
            sincosf(th, &sn, &cs);
            const float z0 = rr * cs, z1 = rr * sn;
            const float rr2 = rr * rr;

            float sumT = 0.0f, sumS = 0.0f;
#pragma unroll
            for (int p = 0; p < 2; p++) {
                unsigned long long v = acc[i][2 * s + p];
                float p0 = ull_lo(v) + (p == 0 ? b2v[s].x : b2v[s].z);
                float p1 = ull_hi(v) + (p == 0 ? b2v[s].y : b2v[s].w);
                float nrm = sqrtf(p0 * p0 + p1 * p1);
                float f = rr * 0.99f / (1.0f + nrm);
                float w0 = f * p0, w1 = f * p1;
                float zw0 = z0 - w0, zw1 = z1 - w1;
                float dist2 = zw0 * zw0 + zw1 * zw1;
                float scale = (rr2 - (w0 * w0 + w1 * w1)) / dist2;
                float zo0 = scale * zw0 - w0;
                float zo1 = scale * zw1 - w1;
                float ang = atan2f(zo1, zo0);
                if (ang < 0.0f) ang += TWO_PI_F;
                sumT += ang;
                sumS += scale;
            }
            // reduce across the 4 lanes owning this d (8 centers total)
            sumT += __shfl_xor_sync(0xffffffffu, sumT, 1);
            sumS += __shfl_xor_sync(0xffffffffu, sumS, 1);
            sumT += __shfl_xor_sync(0xffffffffu, sumT, 2);
            sumS += __shfl_xor_sync(0xffffffffu, sumS, 2);
            if (pgrp == 0) {
                out[grow * D_HALVE + d] = sumT * 0.125f;
                out[(size_t)B_TOTAL * D_HALVE + grow * D_HALVE + d] =
                    logf(sumS * 0.125f + 1e-8f);
            }
        }
    }
}

extern "C" void kernel_launch(void* const* d_in, const int* in_sizes, int n_in,
                              void* d_out, int out_size) {
    const float* theta = (const float*)d_in[0];
    const float* r     = (const float*)d_in[1];
    const float* x     = (const float*)d_in[2];
    const float* W1    = (const float*)d_in[3];
    const float* b1    = (const float*)d_in[4];
    const float* W2    = (const float*)d_in[5];
    const float* b2    = (const float*)d_in[6];
    const float* eta   = (const float*)d_in[7];
    float* out = (float*)d_out;

    pack_w2_kernel<<<(H_DIM * NCOL) / 256, 256>>>(W2, eta);

    const int smem_bytes = (64 * 512 + 64 * 64 + 2 * 8 * 512) * 4;  // 180224
    cudaFuncSetAttribute(moebius_fused_kernel,
                         cudaFuncAttributeMaxDynamicSharedMemorySize, smem_bytes);
    moebius_fused_kernel<<<B_TOTAL / 64, 256, smem_bytes>>>(
        theta, r, x, W1, b1, b2, eta, out);
}

// round 2
// speedup vs baseline: 1.0210x; 1.0210x over previous
#include <cuda_runtime.h>
#include <math.h>
#include <stdint.h>

// Problem constants
#define B_TOTAL   131072
#define DCOND     64
#define H_DIM     512
#define NOUT      513       // W2 column count (last col = unused bias)
#define NCOL      512       // used param columns
#define D_HALVE   32
#define TWO_PI_F  6.283185307179586f

// Packed (eta-folded, stride-512, 16B-aligned) copy of W2
__device__ float g_W2p[H_DIM * NCOL];

__global__ void pack_w2_kernel(const float* __restrict__ W2,
                               const float* __restrict__ eta) {
    int i = blockIdx.x * blockDim.x + threadIdx.x;   // over 512*512
    float e = eta[0];
    int k = i >> 9;
    int c = i & 511;
    g_W2p[i] = W2[k * NOUT + c] * e;
}

__device__ __forceinline__ float ull_lo(unsigned long long v) {
    return __uint_as_float((unsigned int)(v & 0xffffffffull));
}
__device__ __forceinline__ float ull_hi(unsigned long long v) {
    return __uint_as_float((unsigned int)(v >> 32));
}

// ---------------------------------------------------------------------------
// Double-buffered K-staged GEMM accumulate phase (cp.async pipelined).
//   gsrc : [NT*8][512] fp32 row-major, 16B aligned (global)
//   asrc : smem activations, asrc[(8*rg+i)*AS + k]
//   stage: smem [2][8*512] staging buffers
//   acc  : 8 rows x 4 ull (= 8 fp32 cols: 4*cg+{0..3}, 4*cg+256+{0..3})
// ---------------------------------------------------------------------------
template <int NT, int AS>
__device__ __forceinline__ void gemm_phase(const float* __restrict__ gsrc,
                                           const float* __restrict__ asrc,
                                           float* stage,
                                           unsigned long long (&acc)[8][4],
                                           int rg, int cg, int tid) {
    unsigned stage_sa = (unsigned)__cvta_generic_to_shared(stage);

    // prologue: prefetch tile 0
    {
        const char* g = (const char*)gsrc;
#pragma unroll
        for (int j = 0; j < 2; j++) {
            unsigned dst = stage_sa + (unsigned)(tid + 512 * j) * 16u;
            const char* src = g + (size_t)(tid + 512 * j) * 16;
            asm volatile("cp.async.cg.shared.global [%0], [%1], 16;"
                         :: "r"(dst), "l"(src));
        }
        asm volatile("cp.async.commit_group;");
    }

    for (int t = 0; t < NT; t++) {
        if (t + 1 < NT) {
            // prefetch tile t+1 (buffer (t+1)&1 was last read two tiles ago,
            // protected by the trailing barrier below)
            const char* g = (const char*)gsrc + (size_t)(t + 1) * 16384;
#pragma unroll
            for (int j = 0; j < 2; j++) {
                unsigned dst = stage_sa + (unsigned)(((t + 1) & 1) * 16384) +
                               (unsigned)(tid + 512 * j) * 16u;
                const char* src = g + (size_t)(tid + 512 * j) * 16;
                asm volatile("cp.async.cg.shared.global [%0], [%1], 16;"
                             :: "r"(dst), "l"(src));
            }
            asm volatile("cp.async.commit_group;");
            asm volatile("cp.async.wait_group 1;");   // tile t arrived
        } else {
            asm volatile("cp.async.wait_group 0;");
        }
        __syncthreads();   // tile t visible to all threads

        const float* cur = stage + (t & 1) * 4096;
        const ulonglong2* bu = reinterpret_cast<const ulonglong2*>(cur);

#pragma unroll
        for (int kc = 0; kc < 4; kc++) {           // 2 k-values per chunk
            float2 av[8];
#pragma unroll
            for (int i = 0; i < 8; i++)
                av[i] = *reinterpret_cast<const float2*>(
                    &asrc[(8 * rg + i) * AS + t * 8 + 2 * kc]);
#pragma unroll
            for (int kk = 0; kk < 2; kk++) {
                ulonglong2 u0 = bu[(2 * kc + kk) * 128 + cg];
                ulonglong2 u1 = bu[(2 * kc + kk) * 128 + cg + 64];
                unsigned long long bv0 = u0.x, bv1 = u0.y;
                unsigned long long bv2 = u1.x, bv3 = u1.y;
#pragma unroll
                for (int i = 0; i < 8; i++) {
                    unsigned au = __float_as_uint(kk ? av[i].y : av[i].x);
                    unsigned long long a2;
                    asm("mov.b64 %0, {%1, %1};" : "=l"(a2) : "r"(au));
                    asm("fma.rn.f32x2 %0, %1, %2, %0;"
                        : "+l"(acc[i][0]) : "l"(a2), "l"(bv0));
                    asm("fma.rn.f32x2 %0, %1, %2, %0;"
                        : "+l"(acc[i][1]) : "l"(a2), "l"(bv1));
                    asm("fma.rn.f32x2 %0, %1, %2, %0;"
                        : "+l"(acc[i][2]) : "l"(a2), "l"(bv2));
                    asm("fma.rn.f32x2 %0, %1, %2, %0;"
                        : "+l"(acc[i][3]) : "l"(a2), "l"(bv3));
                }
            }
        }
        __syncthreads();   // everyone done reading buf t&1 before it's refilled
    }
}

// ---------------------------------------------------------------------------
// Fused kernel: 64 rows per CTA, 512 threads, 1 CTA/SM, 4 warps/SMSP.
// Thread (rg = tid/64, cg = tid%64) owns rows {8*rg+i} and param columns
// {4*cg+j, 4*cg+256+j | j<4}  ->  dims d0=cg>>2, d1=d0+16,
// centers 2*(cg&3), 2*(cg&3)+1 (both components).
// ---------------------------------------------------------------------------
__global__ __launch_bounds__(512, 1)
void moebius_fused_kernel(const float* __restrict__ theta,
                          const float* __restrict__ r_in,
                          const float* __restrict__ x_cond,
                          const float* __restrict__ W1,
                          const float* __restrict__ b1,
                          const float* __restrict__ b2,
                          const float* __restrict__ eta,
                          float* __restrict__ out) {
    extern __shared__ float smem[];
    float* h_s   = smem;                       // [64][512]  128 KB
    float* x_s   = smem + 64 * 512;            // [64][64]    16 KB
    float* stage = smem + 64 * 512 + 64 * 64;  // [2][8*512]  32 KB

    const int tid = threadIdx.x;
    const int rg = tid >> 6;     // 0..7  (uniform within each warp)
    const int cg = tid & 63;     // 0..63 (contiguous within warp)
    const int blockRow = blockIdx.x * 64;

    // load x tile (coalesced, 2 float4 per thread)
    {
        const float4* xg = reinterpret_cast<const float4*>(x_cond + blockRow * DCOND);
        float4* xs4 = reinterpret_cast<float4*>(x_s);
#pragma unroll
        for (int j = 0; j < 2; j++) xs4[tid + 512 * j] = xg[tid + 512 * j];
    }

    unsigned long long acc[8][4];
#pragma unroll
    for (int i = 0; i < 8; i++)
#pragma unroll
        for (int j = 0; j < 4; j++) acc[i][j] = 0ull;

    // ---- phase 1: h = relu(x @ W1 + b1) ----
    // (x_s writes are ordered before reads by the barrier inside gemm_phase)
    gemm_phase<8, 64>(W1, x_s, stage, acc, rg, cg, tid);

    // bias + relu, write h to smem (contiguous float4 across lanes -> conflict-free)
    {
        float4 bb0 = *reinterpret_cast<const float4*>(b1 + 4 * cg);
        float4 bb1 = *reinterpret_cast<const float4*>(b1 + 4 * cg + 256);
#pragma unroll
        for (int i = 0; i < 8; i++) {
            float4 v0 = make_float4(
                fmaxf(ull_lo(acc[i][0]) + bb0.x, 0.0f),
                fmaxf(ull_hi(acc[i][0]) + bb0.y, 0.0f),
                fmaxf(ull_lo(acc[i][1]) + bb0.z, 0.0f),
                fmaxf(ull_hi(acc[i][1]) + bb0.w, 0.0f));
            float4 v1 = make_float4(
                fmaxf(ull_lo(acc[i][2]) + bb1.x, 0.0f),
                fmaxf(ull_hi(acc[i][2]) + bb1.y, 0.0f),
                fmaxf(ull_lo(acc[i][3]) + bb1.z, 0.0f),
                fmaxf(ull_hi(acc[i][3]) + bb1.w, 0.0f));
            *reinterpret_cast<float4*>(h_s + (8 * rg + i) * 512 + 4 * cg)       = v0;
            *reinterpret_cast<float4*>(h_s + (8 * rg + i) * 512 + 4 * cg + 256) = v1;
        }
    }
#pragma unroll
    for (int i = 0; i < 8; i++)
#pragma unroll
        for (int j = 0; j < 4; j++) acc[i][j] = 0ull;

    // ---- phase 2: params = h @ (W2*eta) ----
    // (h_s writes ordered before reads by barrier inside gemm_phase)
    gemm_phase<64, 512>(g_W2p, h_s, stage, acc, rg, cg, tid);

    // ---- epilogue: Moebius map + angle mean + log-det ----
    const float e = eta[0];
    float4 b2a = *reinterpret_cast<const float4*>(b2 + 4 * cg);
    float4 b2b = *reinterpret_cast<const float4*>(b2 + 4 * cg + 256);
    b2a.x *= e; b2a.y *= e; b2a.z *= e; b2a.w *= e;
    b2b.x *= e; b2b.y *= e; b2b.z *= e; b2b.w *= e;

    const int d0 = cg >> 2;
    const int pgrp = cg & 3;

#pragma unroll
    for (int i = 0; i < 8; i++) {
        const int grow = blockRow + 8 * rg + i;
#pragma unroll
        for (int half = 0; half < 2; half++) {
            const int d = d0 + 16 * half;
            const float4 bb = half ? b2b : b2a;
            const float th = theta[grow * D_HALVE + d];
            const float rr = r_in[grow * D_HALVE + d];
            float sn, cs;
            sincosf(th, &sn, &cs);
            const float z0 = rr * cs, z1 = rr * sn;
            const float rr2 = rr * rr;

            float sumT = 0.0f, sumS = 0.0f;
#pragma unroll
            for (int p = 0; p < 2; p++) {   // two centers per thread per d
                unsigned long long v = acc[i][2 * half + p];
                float p0 = ull_lo(v) + (p == 0 ? bb.x : bb.z);
                float p1 = ull_hi(v) + (p == 0 ? bb.y : bb.w);
                float nrm = sqrtf(p0 * p0 + p1 * p1);
                float f = rr * 0.99f / (1.0f + nrm);
                float w0 = f * p0, w1 = f * p1;
                float zw0 = z0 - w0, zw1 = z1 - w1;
                float dist2 = zw0 * zw0 + zw1 * zw1;
                float scale = (rr2 - (w0 * w0 + w1 * w1)) / dist2;
                float zo0 = scale * zw0 - w0;
                float zo1 = scale * zw1 - w1;
                float ang = atan2f(zo1, zo0);
                if (ang < 0.0f) ang += TWO_PI_F;
                sumT += ang;
                sumS += scale;
            }
            // reduce across the 4 lanes owning this d (8 centers total)
            sumT += __shfl_xor_sync(0xffffffffu, sumT, 1);
            sumS += __shfl_xor_sync(0xffffffffu, sumS, 1);
            sumT += __shfl_xor_sync(0xffffffffu, sumT, 2);
            sumS += __shfl_xor_sync(0xffffffffu, sumS, 2);
            if (pgrp == 0) {
                out[grow * D_HALVE + d] = sumT * 0.125f;
                out[(size_t)B_TOTAL * D_HALVE + grow * D_HALVE + d] =
                    logf(sumS * 0.125f + 1e-8f);
            }
        }
    }
}

extern "C" void kernel_launch(void* const* d_in, const int* in_sizes, int n_in,
                              void* d_out, int out_size) {
    const float* theta = (const float*)d_in[0];
    const float* r     = (const float*)d_in[1];
    const float* x     = (const float*)d_in[2];
    const float* W1    = (const float*)d_in[3];
    const float* b1    = (const float*)d_in[4];
    const float* W2    = (const float*)d_in[5];
    const float* b2    = (const float*)d_in[6];
    const float* eta   = (const float*)d_in[7];
    float* out = (float*)d_out;

    pack_w2_kernel<<<(H_DIM * NCOL) / 256, 256>>>(W2, eta);

    const int smem_bytes = (64 * 512 + 64 * 64 + 2 * 8 * 512) * 4;  // 180224
    cudaFuncSetAttribute(moebius_fused_kernel,
                         cudaFuncAttributeMaxDynamicSharedMemorySize, smem_bytes);
    moebius_fused_kernel<<<B_TOTAL / 64, 512, smem_bytes>>>(
        theta, r, x, W1, b1, b2, eta, out);
}

// round 3
// speedup vs baseline: 1.0222x; 1.0012x over previous
#include <cuda_runtime.h>
#include <math.h>
#include <stdint.h>

// Problem constants
#define B_TOTAL   131072
#define DCOND     64
#define H_DIM     512
#define NOUT      513       // W2 column count (last col = unused bias)
#define NCOL      512       // used param columns
#define D_HALVE   32
#define TWO_PI_F  6.283185307179586f

// Packed (eta-folded, stride-512, 16B-aligned) copy of W2
__device__ float g_W2p[H_DIM * NCOL];

__global__ void pack_w2_kernel(const float* __restrict__ W2,
                               const float* __restrict__ eta) {
    int i = blockIdx.x * blockDim.x + threadIdx.x;   // over 512*512
    float e = eta[0];
    int k = i >> 9;
    int c = i & 511;
    g_W2p[i] = W2[k * NOUT + c] * e;
}

__device__ __forceinline__ float ull_lo(unsigned long long v) {
    return __uint_as_float((unsigned int)(v & 0xffffffffull));
}
__device__ __forceinline__ float ull_hi(unsigned long long v) {
    return __uint_as_float((unsigned int)(v >> 32));
}

// ---------------------------------------------------------------------------
// Double-buffered K-staged GEMM accumulate phase (cp.async pipelined).
//   gsrc : [NT*8][512] fp32 row-major, 16B aligned (global)
//   asrc : smem activations, asrc[(8*rg+i)*AS + k]
//   stage: smem [2][8*512] staging buffers
//   acc  : 8 rows x 4 ull (= 8 fp32 cols: 4*cg+{0..3}, 4*cg+256+{0..3})
// ---------------------------------------------------------------------------
template <int NT, int AS>
__device__ __forceinline__ void gemm_phase(const float* __restrict__ gsrc,
                                           const float* __restrict__ asrc,
                                           float* stage,
                                           unsigned long long (&acc)[8][4],
                                           int rg, int cg, int tid) {
    unsigned stage_sa = (unsigned)__cvta_generic_to_shared(stage);

    // prologue: prefetch tile 0
    {
        const char* g = (const char*)gsrc;
#pragma unroll
        for (int j = 0; j < 2; j++) {
            unsigned dst = stage_sa + (unsigned)(tid + 512 * j) * 16u;
            const char* src = g + (size_t)(tid + 512 * j) * 16;
            asm volatile("cp.async.cg.shared.global [%0], [%1], 16;"
                         :: "r"(dst), "l"(src));
        }
        asm volatile("cp.async.commit_group;");
    }

    for (int t = 0; t < NT; t++) {
        if (t + 1 < NT) {
            // prefetch tile t+1 (buffer (t+1)&1 was last read two tiles ago,
            // protected by the trailing barrier below)
            const char* g = (const char*)gsrc + (size_t)(t + 1) * 16384;
#pragma unroll
            for (int j = 0; j < 2; j++) {
                unsigned dst = stage_sa + (unsigned)(((t + 1) & 1) * 16384) +
                               (unsigned)(tid + 512 * j) * 16u;
                const char* src = g + (size_t)(tid + 512 * j) * 16;
                asm volatile("cp.async.cg.shared.global [%0], [%1], 16;"
                             :: "r"(dst), "l"(src));
            }
            asm volatile("cp.async.commit_group;");
            asm volatile("cp.async.wait_group 1;");   // tile t arrived
        } else {
            asm volatile("cp.async.wait_group 0;");
        }
        __syncthreads();   // tile t visible to all threads

        const float* cur = stage + (t & 1) * 4096;
        const ulonglong2* bu = reinterpret_cast<const ulonglong2*>(cur);

#pragma unroll
        for (int kc = 0; kc < 4; kc++) {           // 2 k-values per chunk
            float2 av[8];
#pragma unroll
            for (int i = 0; i < 8; i++)
                av[i] = *reinterpret_cast<const float2*>(
                    &asrc[(8 * rg + i) * AS + t * 8 + 2 * kc]);
#pragma unroll
            for (int kk = 0; kk < 2; kk++) {
                ulonglong2 u0 = bu[(2 * kc + kk) * 128 + cg];
                ulonglong2 u1 = bu[(2 * kc + kk) * 128 + cg + 64];
                unsigned long long bv0 = u0.x, bv1 = u0.y;
                unsigned long long bv2 = u1.x, bv3 = u1.y;
#pragma unroll
                for (int i = 0; i < 8; i++) {
                    unsigned au = __float_as_uint(kk ? av[i].y : av[i].x);
                    unsigned long long a2;
                    asm("mov.b64 %0, {%1, %1};" : "=l"(a2) : "r"(au));
                    asm("fma.rn.f32x2 %0, %1, %2, %0;"
                        : "+l"(acc[i][0]) : "l"(a2), "l"(bv0));
                    asm("fma.rn.f32x2 %0, %1, %2, %0;"
                        : "+l"(acc[i][1]) : "l"(a2), "l"(bv1));
                    asm("fma.rn.f32x2 %0, %1, %2, %0;"
                        : "+l"(acc[i][2]) : "l"(a2), "l"(bv2));
                    asm("fma.rn.f32x2 %0, %1, %2, %0;"
                        : "+l"(acc[i][3]) : "l"(a2), "l"(bv3));
                }
            }
        }
        __syncthreads();   // everyone done reading buf t&1 before it's refilled
    }
}

// ---------------------------------------------------------------------------
// Fused kernel: 64 rows per CTA, 512 threads, 1 CTA/SM, 4 warps/SMSP.
// Thread (rg = tid/64, cg = tid%64) owns rows {8*rg+i} and param columns
// {4*cg+j, 4*cg+256+j | j<4}  ->  dims d0=cg>>2, d1=d0+16,
// centers 2*(cg&3), 2*(cg&3)+1 (both components).
// ---------------------------------------------------------------------------
__global__ __launch_bounds__(512, 1)
void moebius_fused_kernel(const float* __restrict__ theta,
                          const float* __restrict__ r_in,
                          const float* __restrict__ x_cond,
                          const float* __restrict__ W1,
                          const float* __restrict__ b1,
                          const float* __restrict__ b2,
                          const float* __restrict__ eta,
                          float* __restrict__ out) {
    extern __shared__ float smem[];
    float* h_s   = smem;                       // [64][512]  128 KB
    float* x_s   = smem + 64 * 512;            // [64][64]    16 KB
    float* stage = smem + 64 * 512 + 64 * 64;  // [2][8*512]  32 KB

    const int tid = threadIdx.x;
    const int rg = tid >> 6;     // 0..7  (uniform within each warp)
    const int cg = tid & 63;     // 0..63 (contiguous within warp)
    const int blockRow = blockIdx.x * 64;

    // load x tile (coalesced, 2 float4 per thread)
    {
        const float4* xg = reinterpret_cast<const float4*>(x_cond + blockRow * DCOND);
        float4* xs4 = reinterpret_cast<float4*>(x_s);
#pragma unroll
        for (int j = 0; j < 2; j++) xs4[tid + 512 * j] = xg[tid + 512 * j];
    }

    unsigned long long acc[8][4];
#pragma unroll
    for (int i = 0; i < 8; i++)
#pragma unroll
        for (int j = 0; j < 4; j++) acc[i][j] = 0ull;

    // ---- phase 1: h = relu(x @ W1 + b1) ----
    // (x_s writes are ordered before reads by the barrier inside gemm_phase)
    gemm_phase<8, 64>(W1, x_s, stage, acc, rg, cg, tid);

    // bias + relu, write h to smem (contiguous float4 across lanes -> conflict-free)
    {
        float4 bb0 = *reinterpret_cast<const float4*>(b1 + 4 * cg);
        float4 bb1 = *reinterpret_cast<const float4*>(b1 + 4 * cg + 256);
#pragma unroll
        for (int i = 0; i < 8; i++) {
            float4 v0 = make_float4(
                fmaxf(ull_lo(acc[i][0]) + bb0.x, 0.0f),
                fmaxf(ull_hi(acc[i][0]) + bb0.y, 0.0f),
                fmaxf(ull_lo(acc[i][1]) + bb0.z, 0.0f),
                fmaxf(ull_hi(acc[i][1]) + bb0.w, 0.0f));
            float4 v1 = make_float4(
                fmaxf(ull_lo(acc[i][2]) + bb1.x, 0.0f),
                fmaxf(ull_hi(acc[i][2]) + bb1.y, 0.0f),
                fmaxf(ull_lo(acc[i][3]) + bb1.z, 0.0f),
                fmaxf(ull_hi(acc[i][3]) + bb1.w, 0.0f));
            *reinterpret_cast<float4*>(h_s + (8 * rg + i) * 512 + 4 * cg)       = v0;
            *reinterpret_cast<float4*>(h_s + (8 * rg + i) * 512 + 4 * cg + 256) = v1;
        }
    }
#pragma unroll
    for (int i = 0; i < 8; i++)
#pragma unroll
        for (int j = 0; j < 4; j++) acc[i][j] = 0ull;

    // ---- phase 2: params = h @ (W2*eta) ----
    // (h_s writes ordered before reads by barrier inside gemm_phase)
    gemm_phase<64, 512>(g_W2p, h_s, stage, acc, rg, cg, tid);

    // ---- epilogue: Moebius map + angle mean + log-det ----
    const float e = eta[0];
    float4 b2a = *reinterpret_cast<const float4*>(b2 + 4 * cg);
    float4 b2b = *reinterpret_cast<const float4*>(b2 + 4 * cg + 256);
    b2a.x *= e; b2a.y *= e; b2a.z *= e; b2a.w *= e;
    b2b.x *= e; b2b.y *= e; b2b.z *= e; b2b.w *= e;

    const int d0 = cg >> 2;
    const int pgrp = cg & 3;

#pragma unroll
    for (int i = 0; i < 8; i++) {
        const int grow = blockRow + 8 * rg + i;
#pragma unroll
        for (int half = 0; half < 2; half++) {
            const int d = d0 + 16 * half;
            const float4 bb = half ? b2b : b2a;
            const float th = theta[grow * D_HALVE + d];
            const float rr = r_in[grow * D_HALVE + d];
            float sn, cs;
            sincosf(th, &sn, &cs);
            const float z0 = rr * cs, z1 = rr * sn;
            const float rr2 = rr * rr;

            float sumT = 0.0f, sumS = 0.0f;
#pragma unroll
            for (int p = 0; p < 2; p++) {   // two centers per thread per d
                unsigned long long v = acc[i][2 * half + p];
                float p0 = ull_lo(v) + (p == 0 ? bb.x : bb.z);
                float p1 = ull_hi(v) + (p == 0 ? bb.y : bb.w);
                float nrm = sqrtf(p0 * p0 + p1 * p1);
                float f = rr * 0.99f / (1.0f + nrm);
                float w0 = f * p0, w1 = f * p1;
                float zw0 = z0 - w0, zw1 = z1 - w1;
                float dist2 = zw0 * zw0 + zw1 * zw1;
                float scale = (rr2 - (w0 * w0 + w1 * w1)) / dist2;
                float zo0 = scale * zw0 - w0;
                float zo1 = scale * zw1 - w1;
                float ang = atan2f(zo1, zo0);
                if (ang < 0.0f) ang += TWO_PI_F;
                sumT += ang;
                sumS += scale;
            }
            // reduce across the 4 lanes owning this d (8 centers total)
            sumT += __shfl_xor_sync(0xffffffffu, sumT, 1);
            sumS += __shfl_xor_sync(0xffffffffu, sumS, 1);
            sumT += __shfl_xor_sync(0xffffffffu, sumT, 2);
            sumS += __shfl_xor_sync(0xffffffffu, sumS, 2);
            if (pgrp == 0) {
                out[grow * D_HALVE + d] = sumT * 0.125f;
                out[(size_t)B_TOTAL * D_HALVE + grow * D_HALVE + d] =
                    logf(sumS * 0.125f + 1e-8f);
            }
        }
    }
}

extern "C" void kernel_launch(void* const* d_in, const int* in_sizes, int n_in,
                              void* d_out, int out_size) {
    const float* theta = (const float*)d_in[0];
    const float* r     = (const float*)d_in[1];
    const float* x     = (const float*)d_in[2];
    const float* W1    = (const float*)d_in[3];
    const float* b1    = (const float*)d_in[4];
    const float* W2    = (const float*)d_in[5];
    const float* b2    = (const float*)d_in[6];
    const float* eta   = (const float*)d_in[7];
    float* out = (float*)d_out;

    pack_w2_kernel<<<(H_DIM * NCOL) / 256, 256>>>(W2, eta);

    const int smem_bytes = (64 * 512 + 64 * 64 + 2 * 8 * 512) * 4;  // 180224
    cudaFuncSetAttribute(moebius_fused_kernel,
                         cudaFuncAttributeMaxDynamicSharedMemorySize, smem_bytes);
    moebius_fused_kernel<<<B_TOTAL / 64, 512, smem_bytes>>>(
        theta, r, x, W1, b1, b2, eta, out);
}

// round 6
// speedup vs baseline: 1.5132x; 1.4803x over previous
#include <cuda_runtime.h>
#include <cuda_fp16.h>
#include <math.h>
#include <stdint.h>

// ---------------- problem constants ----------------
#define B_TOTAL   131072
#define DH        32
#define TWO_PI_F  6.283185307179586f

// ---------------- device scratch (static, no alloc) ----------------
__device__ __half g_xhi[(size_t)B_TOTAL * 64];
__device__ __half g_xlo[(size_t)B_TOTAL * 64];
__device__ __half g_hhi[(size_t)B_TOTAL * 512];
__device__ __half g_hlo[(size_t)B_TOTAL * 512];
__device__ __half g_w1hi[512 * 64];    // W1^T [n=512][k=64]
__device__ __half g_w1lo[512 * 64];
__device__ __half g_w2hi[512 * 512];   // (W2*eta)^T [n=512][k=512]
__device__ __half g_w2lo[512 * 512];

__device__ __forceinline__ void split_h(float v, __half& hi, __half& lo) {
    hi = __float2half_rn(v);
    lo = __float2half_rn(v - __half2float(hi));
}

// ---------------- pack kernels ----------------
__global__ void pack_x_kernel(const float* __restrict__ x) {
    size_t i = (size_t)blockIdx.x * blockDim.x + threadIdx.x;  // B*64
    __half hi, lo;
    split_h(x[i], hi, lo);
    g_xhi[i] = hi;
    g_xlo[i] = lo;
}
__global__ void pack_w1_kernel(const float* __restrict__ W1) {
    int i = blockIdx.x * blockDim.x + threadIdx.x;   // 512*64
    int n = i >> 6, k = i & 63;
    __half hi, lo;
    split_h(W1[k * 512 + n], hi, lo);
    g_w1hi[i] = hi;    // [n][k] layout, i = n*64+k
    g_w1lo[i] = lo;
}
__global__ void pack_w2_kernel(const float* __restrict__ W2,
                               const float* __restrict__ eta) {
    int i = blockIdx.x * blockDim.x + threadIdx.x;   // 512*512
    int n = i >> 9, k = i & 511;
    __half hi, lo;
    split_h(W2[k * 513 + n] * eta[0], hi, lo);
    g_w2hi[i] = hi;    // [n][k], i = n*512+k
    g_w2lo[i] = lo;
}

// ---------------------------------------------------------------------------
// fp16x3-split GEMM via mma.sync m16n8k16 (row.col, fp32 accum).
// CTA: 256 threads (8 warps), output tile M=128 x N=256.
// Warp grid 2(m) x 4(n): warp tile 64x64 -> acc[4 mi][8 nj][4] fp32.
// K' = 3*KSEG as segments: A' = [Ahi|Ahi|Alo], B' = [Bhi|Blo|Bhi].
// Staging: k64 chunks, A 16KB + B 32KB, double buffered (96KB smem),
// 16B-XOR swizzle for conflict-free ldmatrix.
// PHASE1: A=x splits, B=W1^T splits, epilogue relu+split -> g_h{hi,lo}
// PHASE2: A=h splits, B=(W2*eta)^T splits, epilogue Moebius -> out
// ---------------------------------------------------------------------------
template <int KSEG, bool PHASE1>
__global__ __launch_bounds__(256, 1)
void mma_gemm_kernel(const float* __restrict__ bias,
                     const float* __restrict__ theta,
                     const float* __restrict__ r_in,
                     const float* __restrict__ eta,
                     float* __restrict__ out) {
    constexpr int CPS = KSEG / 64;      // chunks per segment
    constexpr int NC = 3 * CPS;         // total chunks
    constexpr int SSTRIDE = KSEG * 2;   // source row stride (bytes)

    extern __shared__ char smem[];
    const uint32_t sbase = (uint32_t)__cvta_generic_to_shared(smem);

    const int tid = threadIdx.x;
    const int lane = tid & 31;
    const int wid = tid >> 5;
    const int wm = (wid & 1) * 64;       // warp M offset within CTA tile
    const int wn = (wid >> 1) * 64;      // warp N offset within CTA tile
    const int blockRow = blockIdx.x * 128;
    const int colbase = blockIdx.y * 256;

    const __half* Ahi = PHASE1 ? g_xhi : g_hhi;
    const __half* Alo = PHASE1 ? g_xlo : g_hlo;
    const __half* Bhi = PHASE1 ? g_w1hi : g_w2hi;
    const __half* Blo = PHASE1 ? g_w1lo : g_w2lo;

    float acc[4][8][4];
#pragma unroll
    for (int mi = 0; mi < 4; mi++)
#pragma unroll
        for (int nj = 0; nj < 8; nj++)
#pragma unroll
            for (int q = 0; q < 4; q++) acc[mi][nj][q] = 0.0f;

    // ldmatrix lane-address components.
    // A (m16x k16 per x4): lane bit3 -> +8 rows, bit4 -> +8 k-halves.
    const int aRow = wm + (lane & 7) + ((lane >> 3) & 1) * 8;
    const int aU = (lane >> 4) & 1;
    const int aX = aRow & 7;
    // B (two n8 x k16 per x4): bit4 -> +8 n-rows, bit3 -> +8 k-halves.
    const int bRow = wn + (lane & 7) + ((lane >> 4) & 1) * 8;
    const int bU = (lane >> 3) & 1;
    const int bX = bRow & 7;

    auto loadc = [&](int c) {
        int seg = c / CPS;
        int kc = c - seg * CPS;
        const char* ag = (const char*)(seg == 2 ? Alo : Ahi) +
                         (size_t)blockRow * SSTRIDE + (size_t)kc * 128;
        const char* bg = (const char*)(seg == 1 ? Blo : Bhi) +
                         (size_t)colbase * SSTRIDE + (size_t)kc * 128;
        uint32_t ab = sbase + (uint32_t)(c & 1) * 49152u;
        uint32_t bb = ab + 16384u;
#pragma unroll
        for (int j = 0; j < 4; j++) {                 // A: 1024 x 16B units
            int gi = tid + 256 * j;
            int row = gi >> 3, u = gi & 7;
            const char* src = ag + (size_t)row * SSTRIDE + u * 16;
            uint32_t dst = ab + row * 128u + (uint32_t)((u ^ (row & 7)) << 4);
            asm volatile("cp.async.cg.shared.global [%0], [%1], 16;"
                         :: "r"(dst), "l"(src));
        }
#pragma unroll
        for (int j = 0; j < 8; j++) {                 // B: 2048 x 16B units
            int gi = tid + 256 * j;
            int row = gi >> 3, u = gi & 7;
            const char* src = bg + (size_t)row * SSTRIDE + u * 16;
            uint32_t dst = bb + row * 128u + (uint32_t)((u ^ (row & 7)) << 4);
            asm volatile("cp.async.cg.shared.global [%0], [%1], 16;"
                         :: "r"(dst), "l"(src));
        }
        asm volatile("cp.async.commit_group;");
    };

    loadc(0);
#pragma unroll 1
    for (int c = 0; c < NC; c++) {
        if (c + 1 < NC) {
            loadc(c + 1);                              // opposite buffer, freed
            asm volatile("cp.async.wait_group 1;");    // by prev iter's barrier
        } else {
            asm volatile("cp.async.wait_group 0;");
        }
        __syncthreads();

        uint32_t ab = sbase + (uint32_t)(c & 1) * 49152u;
        uint32_t bb = ab + 16384u;
#pragma unroll
        for (int kk = 0; kk < 4; kk++) {
            uint32_t a[4][4];
#pragma unroll
            for (int mi = 0; mi < 4; mi++) {
                int row = aRow + mi * 16;
                uint32_t addr = ab + row * 128u +
                                (uint32_t)(((kk * 2 + aU) ^ aX) << 4);
                asm volatile(
                    "ldmatrix.sync.aligned.m8n8.x4.shared.b16 {%0,%1,%2,%3}, [%4];"
                    : "=r"(a[mi][0]), "=r"(a[mi][1]), "=r"(a[mi][2]), "=r"(a[mi][3])
                    : "r"(addr));
            }
            uint32_t b[8][2];
#pragma unroll
            for (int p = 0; p < 4; p++) {
                int row = bRow + p * 16;
                uint32_t addr = bb + row * 128u +
                                (uint32_t)(((kk * 2 + bU) ^ bX) << 4);
                asm volatile(
                    "ldmatrix.sync.aligned.m8n8.x4.shared.b16 {%0,%1,%2,%3}, [%4];"
                    : "=r"(b[2 * p][0]), "=r"(b[2 * p][1]),
                      "=r"(b[2 * p + 1][0]), "=r"(b[2 * p + 1][1])
                    : "r"(addr));
            }
#pragma unroll
            for (int mi = 0; mi < 4; mi++)
#pragma unroll
                for (int nj = 0; nj < 8; nj++) {
                    asm volatile(
                        "mma.sync.aligned.m16n8k16.row.col.f32.f16.f16.f32 "
                        "{%0,%1,%2,%3}, {%4,%5,%6,%7}, {%8,%9}, {%0,%1,%2,%3};"
                        : "+f"(acc[mi][nj][0]), "+f"(acc[mi][nj][1]),
                          "+f"(acc[mi][nj][2]), "+f"(acc[mi][nj][3])
                        : "r"(a[mi][0]), "r"(a[mi][1]), "r"(a[mi][2]), "r"(a[mi][3]),
                          "r"(b[nj][0]), "r"(b[nj][1]));
                }
        }
        __syncthreads();   // all warps done with buffer (c&1) before refill
    }

    // ---- epilogue ----
    const int g = lane >> 2;       // row within m16 half
    const int tig = lane & 3;      // col pair within n8

    if constexpr (PHASE1) {
#pragma unroll
        for (int mi = 0; mi < 4; mi++)
#pragma unroll
            for (int rsel = 0; rsel < 2; rsel++) {
                int grow = blockRow + wm + mi * 16 + g + rsel * 8;
#pragma unroll
                for (int nj = 0; nj < 8; nj++) {
                    int cc = colbase + wn + nj * 8 + 2 * tig;
                    float h0 = fmaxf(acc[mi][nj][rsel * 2 + 0] + bias[cc], 0.0f);
                    float h1 = fmaxf(acc[mi][nj][rsel * 2 + 1] + bias[cc + 1], 0.0f);
                    __half hi0, lo0, hi1, lo1;
                    split_h(h0, hi0, lo0);
                    split_h(h1, hi1, lo1);
                    *reinterpret_cast<__half2*>(&g_hhi[(size_t)grow * 512 + cc]) =
                        __halves2half2(hi0, hi1);
                    *reinterpret_cast<__half2*>(&g_hlo[(size_t)grow * 512 + cc]) =
                        __halves2half2(lo0, lo1);
                }
            }
    } else {
        const float e = eta[0];
        float bb2[8][2];
#pragma unroll
        for (int nj = 0; nj < 8; nj++) {
            int cc = colbase + wn + nj * 8 + 2 * tig;
            bb2[nj][0] = bias[cc] * e;
            bb2[nj][1] = bias[cc + 1] * e;
        }
        const int dbase = (colbase + wn) >> 4;

#pragma unroll
        for (int mi = 0; mi < 4; mi++)
#pragma unroll
            for (int rsel = 0; rsel < 2; rsel++) {
                int grow = blockRow + wm + mi * 16 + g + rsel * 8;
#pragma unroll
                for (int dj = 0; dj < 4; dj++) {
                    int d = dbase + dj;
                    float th = theta[grow * DH + d];
                    float rr = r_in[grow * DH + d];
                    float sn, cs;
                    sincosf(th, &sn, &cs);
                    float z0 = rr * cs, z1 = rr * sn;
                    float rr2 = rr * rr;
                    float sumT = 0.0f, sumS = 0.0f;
#pragma unroll
                    for (int hf = 0; hf < 2; hf++) {
                        int nj = 2 * dj + hf;
                        float p0 = acc[mi][nj][rsel * 2 + 0] + bb2[nj][0];
                        float p1 = acc[mi][nj][rsel * 2 + 1] + bb2[nj][1];
                        float nrm = sqrtf(p0 * p0 + p1 * p1);
                        float f = rr * 0.99f / (1.0f + nrm);
                        float w0 = f * p0, w1 = f * p1;
                        float zw0 = z0 - w0, zw1 = z1 - w1;
                        float dist2 = zw0 * zw0 + zw1 * zw1;
                        float scale = (rr2 - (w0 * w0 + w1 * w1)) / dist2;
                        float zo0 = scale * zw0 - w0;
                        float zo1 = scale * zw1 - w1;
                        float ang = atan2f(zo1, zo0);
                        if (ang < 0.0f) ang += TWO_PI_F;
                        sumT += ang;
                        sumS += scale;
                    }
                    sumT += __shfl_xor_sync(0xffffffffu, sumT, 1);
                    sumS += __shfl_xor_sync(0xffffffffu, sumS, 1);
                    sumT += __shfl_xor_sync(0xffffffffu, sumT, 2);
                    sumS += __shfl_xor_sync(0xffffffffu, sumS, 2);
                    if (tig == 0) {
                        out[grow * DH + d] = sumT * 0.125f;
                        out[(size_t)B_TOTAL * DH + grow * DH + d] =
                            logf(sumS * 0.125f + 1e-8f);
                    }
                }
            }
    }
}

// ---------------- launch ----------------
extern "C" void kernel_launch(void* const* d_in, const int* in_sizes, int n_in,
                              void* d_out, int out_size) {
    const float* theta = (const float*)d_in[0];
    const float* r     = (const float*)d_in[1];
    const float* x     = (const float*)d_in[2];
    const float* W1    = (const float*)d_in[3];
    const float* b1    = (const float*)d_in[4];
    const float* W2    = (const float*)d_in[5];
    const float* b2    = (const float*)d_in[6];
    const float* eta   = (const float*)d_in[7];
    float* out = (float*)d_out;

    pack_x_kernel<<<(B_TOTAL * 64) / 256, 256>>>(x);
    pack_w1_kernel<<<(512 * 64) / 256, 256>>>(W1);
    pack_w2_kernel<<<(512 * 512) / 256, 256>>>(W2, eta);

    const int smem_bytes = 2 * 49152;   // 96 KB
    cudaFuncSetAttribute(mma_gemm_kernel<64, true>,
                         cudaFuncAttributeMaxDynamicSharedMemorySize, smem_bytes);
    cudaFuncSetAttribute(mma_gemm_kernel<512, false>,
                         cudaFuncAttributeMaxDynamicSharedMemorySize, smem_bytes);

    dim3 grid(B_TOTAL / 128, 2);
    mma_gemm_kernel<64, true><<<grid, 256, smem_bytes>>>(
        b1, nullptr, nullptr, nullptr, nullptr);
    mma_gemm_kernel<512, false><<<grid, 256, smem_bytes>>>(
        b2, theta, r, eta, out);
}

// round 7
// speedup vs baseline: 1.5533x; 1.0265x over previous
#include <cuda_runtime.h>
#include <cuda_fp16.h>
#include <math.h>
#include <stdint.h>

// ---------------- problem constants ----------------
#define B_TOTAL   131072
#define DH        32
#define TWO_PI_F  6.283185307179586f

// ---------------- device scratch (static, no alloc) ----------------
__device__ __half g_xhi[(size_t)B_TOTAL * 64];
__device__ __half g_xlo[(size_t)B_TOTAL * 64];
__device__ __half g_hhi[(size_t)B_TOTAL * 512];
__device__ __half g_hlo[(size_t)B_TOTAL * 512];
__device__ __half g_w1hi[512 * 64];    // W1^T [n=512][k=64]
__device__ __half g_w1lo[512 * 64];
__device__ __half g_w2hi[512 * 512];   // (W2*eta)^T [n=512][k=512]
__device__ __half g_w2lo[512 * 512];

__device__ __forceinline__ void split_h(float v, __half& hi, __half& lo) {
    hi = __float2half_rn(v);
    lo = __float2half_rn(v - __half2float(hi));
}

// ---------------- pack kernels ----------------
__global__ void pack_x_kernel(const float* __restrict__ x) {
    size_t i = (size_t)blockIdx.x * blockDim.x + threadIdx.x;  // B*64
    __half hi, lo;
    split_h(x[i], hi, lo);
    g_xhi[i] = hi;
    g_xlo[i] = lo;
}
__global__ void pack_w1_kernel(const float* __restrict__ W1) {
    int i = blockIdx.x * blockDim.x + threadIdx.x;   // 512*64
    int n = i >> 6, k = i & 63;
    __half hi, lo;
    split_h(W1[k * 512 + n], hi, lo);
    g_w1hi[i] = hi;    // [n][k] layout, i = n*64+k
    g_w1lo[i] = lo;
}
__global__ void pack_w2_kernel(const float* __restrict__ W2,
                               const float* __restrict__ eta) {
    int i = blockIdx.x * blockDim.x + threadIdx.x;   // 512*512
    int n = i >> 9, k = i & 511;
    __half hi, lo;
    split_h(W2[k * 513 + n] * eta[0], hi, lo);
    g_w2hi[i] = hi;    // [n][k], i = n*512+k
    g_w2lo[i] = lo;
}

// ---------------------------------------------------------------------------
// fp16x3-split GEMM via mma.sync m16n8k16 (row.col, fp32 accum).
// CTA: 256 threads (8 warps), output tile M=128 x N=256.
// Warp grid 2(m) x 4(n): warp tile 64x64 -> acc[4 mi][8 nj][4] fp32.
// K' = 3*KSEG as segments: A' = [Ahi|Ahi|Alo], B' = [Bhi|Blo|Bhi].
// Staging: k64 chunks, A 16KB + B 32KB, 4-stage cp.async pipeline (192KB),
// 16B-XOR swizzle for conflict-free ldmatrix.
// Grid: (2 n-halves, B/128 row-tiles) so row-sharing CTAs are L2-adjacent.
// PHASE1: A=x splits, B=W1^T splits, epilogue relu+split -> g_h{hi,lo}
// PHASE2: A=h splits, B=(W2*eta)^T splits, epilogue Moebius -> out
// ---------------------------------------------------------------------------
template <int KSEG, bool PHASE1>
__global__ __launch_bounds__(256, 1)
void mma_gemm_kernel(const float* __restrict__ bias,
                     const float* __restrict__ theta,
                     const float* __restrict__ r_in,
                     const float* __restrict__ eta,
                     float* __restrict__ out) {
    constexpr int CPS = KSEG / 64;      // chunks per segment
    constexpr int NC = 3 * CPS;         // total chunks
    constexpr int SSTRIDE = KSEG * 2;   // source row stride (bytes)
    constexpr int STAGES = 4;

    extern __shared__ char smem[];
    const uint32_t sbase = (uint32_t)__cvta_generic_to_shared(smem);

    const int tid = threadIdx.x;
    const int lane = tid & 31;
    const int wid = tid >> 5;
    const int wm = (wid & 1) * 64;       // warp M offset within CTA tile
    const int wn = (wid >> 1) * 64;      // warp N offset within CTA tile
    const int blockRow = blockIdx.y * 128;
    const int colbase = blockIdx.x * 256;

    const __half* Ahi = PHASE1 ? g_xhi : g_hhi;
    const __half* Alo = PHASE1 ? g_xlo : g_hlo;
    const __half* Bhi = PHASE1 ? g_w1hi : g_w2hi;
    const __half* Blo = PHASE1 ? g_w1lo : g_w2lo;

    float acc[4][8][4];
#pragma unroll
    for (int mi = 0; mi < 4; mi++)
#pragma unroll
        for (int nj = 0; nj < 8; nj++)
#pragma unroll
            for (int q = 0; q < 4; q++) acc[mi][nj][q] = 0.0f;

    // ldmatrix lane-address components.
    // A (m16 x k16 per x4): lane bit3 -> +8 rows, bit4 -> +8 k-halves.
    const int aRow = wm + (lane & 7) + ((lane >> 3) & 1) * 8;
    const int aU = (lane >> 4) & 1;
    const int aX = aRow & 7;
    // B (two n8 x k16 per x4): bit4 -> +8 n-rows, bit3 -> +8 k-halves.
    const int bRow = wn + (lane & 7) + ((lane >> 4) & 1) * 8;
    const int bU = (lane >> 3) & 1;
    const int bX = bRow & 7;

    auto loadc = [&](int c) {
        int seg = c / CPS;
        int kc = c - seg * CPS;
        const char* ag = (const char*)(seg == 2 ? Alo : Ahi) +
                         (size_t)blockRow * SSTRIDE + (size_t)kc * 128;
        const char* bg = (const char*)(seg == 1 ? Blo : Bhi) +
                         (size_t)colbase * SSTRIDE + (size_t)kc * 128;
        uint32_t ab = sbase + (uint32_t)(c % STAGES) * 49152u;
        uint32_t bb = ab + 16384u;
#pragma unroll
        for (int j = 0; j < 4; j++) {                 // A: 1024 x 16B units
            int gi = tid + 256 * j;
            int row = gi >> 3, u = gi & 7;
            const char* src = ag + (size_t)row * SSTRIDE + u * 16;
            uint32_t dst = ab + row * 128u + (uint32_t)((u ^ (row & 7)) << 4);
            asm volatile("cp.async.cg.shared.global [%0], [%1], 16;"
                         :: "r"(dst), "l"(src));
        }
#pragma unroll
        for (int j = 0; j < 8; j++) {                 // B: 2048 x 16B units
            int gi = tid + 256 * j;
            int row = gi >> 3, u = gi & 7;
            const char* src = bg + (size_t)row * SSTRIDE + u * 16;
            uint32_t dst = bb + row * 128u + (uint32_t)((u ^ (row & 7)) << 4);
            asm volatile("cp.async.cg.shared.global [%0], [%1], 16;"
                         :: "r"(dst), "l"(src));
        }
        asm volatile("cp.async.commit_group;");
    };

    // ---- prologue: fill STAGES-1 buffers (empty groups keep FIFO uniform) ----
#pragma unroll
    for (int s = 0; s < STAGES - 1; s++) {
        if (s < NC) loadc(s);
        else asm volatile("cp.async.commit_group;");
    }
    asm volatile("cp.async.wait_group %0;" :: "n"(STAGES - 2));
    __syncthreads();   // chunk 0 visible

#pragma unroll 1
    for (int c = 0; c < NC; c++) {
        // refill buffer (c-1)%STAGES — its readers passed last iter's barrier
        if (c + STAGES - 1 < NC) loadc(c + STAGES - 1);
        else asm volatile("cp.async.commit_group;");

        uint32_t ab = sbase + (uint32_t)(c % STAGES) * 49152u;
        uint32_t bb = ab + 16384u;
#pragma unroll
        for (int kk = 0; kk < 4; kk++) {
            uint32_t a[4][4];
#pragma unroll
            for (int mi = 0; mi < 4; mi++) {
                int row = aRow + mi * 16;
                uint32_t addr = ab + row * 128u +
                                (uint32_t)(((kk * 2 + aU) ^ aX) << 4);
                asm volatile(
                    "ldmatrix.sync.aligned.m8n8.x4.shared.b16 {%0,%1,%2,%3}, [%4];"
                    : "=r"(a[mi][0]), "=r"(a[mi][1]), "=r"(a[mi][2]), "=r"(a[mi][3])
                    : "r"(addr));
            }
            uint32_t b[8][2];
#pragma unroll
            for (int p = 0; p < 4; p++) {
                int row = bRow + p * 16;
                uint32_t addr = bb + row * 128u +
                                (uint32_t)(((kk * 2 + bU) ^ bX) << 4);
                asm volatile(
                    "ldmatrix.sync.aligned.m8n8.x4.shared.b16 {%0,%1,%2,%3}, [%4];"
                    : "=r"(b[2 * p][0]), "=r"(b[2 * p][1]),
                      "=r"(b[2 * p + 1][0]), "=r"(b[2 * p + 1][1])
                    : "r"(addr));
            }
#pragma unroll
            for (int mi = 0; mi < 4; mi++)
#pragma unroll
                for (int nj = 0; nj < 8; nj++) {
                    asm volatile(
                        "mma.sync.aligned.m16n8k16.row.col.f32.f16.f16.f32 "
                        "{%0,%1,%2,%3}, {%4,%5,%6,%7}, {%8,%9}, {%0,%1,%2,%3};"
                        : "+f"(acc[mi][nj][0]), "+f"(acc[mi][nj][1]),
                          "+f"(acc[mi][nj][2]), "+f"(acc[mi][nj][3])
                        : "r"(a[mi][0]), "r"(a[mi][1]), "r"(a[mi][2]), "r"(a[mi][3]),
                          "r"(b[nj][0]), "r"(b[nj][1]));
                }
        }
        // chunk c+1 complete (pending <= STAGES-2 groups), readers re-synced
        asm volatile("cp.async.wait_group %0;" :: "n"(STAGES - 2));
        __syncthreads();
    }

    // ---- epilogue ----
    const int g = lane >> 2;       // row within m16 half
    const int tig = lane & 3;      // col pair within n8

    if constexpr (PHASE1) {
#pragma unroll
        for (int mi = 0; mi < 4; mi++)
#pragma unroll
            for (int rsel = 0; rsel < 2; rsel++) {
                int grow = blockRow + wm + mi * 16 + g + rsel * 8;
#pragma unroll
                for (int nj = 0; nj < 8; nj++) {
                    int cc = colbase + wn + nj * 8 + 2 * tig;
                    float h0 = fmaxf(acc[mi][nj][rsel * 2 + 0] + bias[cc], 0.0f);
                    float h1 = fmaxf(acc[mi][nj][rsel * 2 + 1] + bias[cc + 1], 0.0f);
                    __half hi0, lo0, hi1, lo1;
                    split_h(h0, hi0, lo0);
                    split_h(h1, hi1, lo1);
                    *reinterpret_cast<__half2*>(&g_hhi[(size_t)grow * 512 + cc]) =
                        __halves2half2(hi0, hi1);
                    *reinterpret_cast<__half2*>(&g_hlo[(size_t)grow * 512 + cc]) =
                        __halves2half2(lo0, lo1);
                }
            }
    } else {
        const float e = eta[0];
        float bb2[8][2];
#pragma unroll
        for (int nj = 0; nj < 8; nj++) {
            int cc = colbase + wn + nj * 8 + 2 * tig;
            bb2[nj][0] = bias[cc] * e;
            bb2[nj][1] = bias[cc + 1] * e;
        }
        const int dbase = (colbase + wn) >> 4;

#pragma unroll
        for (int mi = 0; mi < 4; mi++)
#pragma unroll
            for (int rsel = 0; rsel < 2; rsel++) {
                int grow = blockRow + wm + mi * 16 + g + rsel * 8;
#pragma unroll
                for (int dj = 0; dj < 4; dj++) {
                    int d = dbase + dj;
                    float th = theta[grow * DH + d];
                    float rr = r_in[grow * DH + d];
                    float sn, cs;
                    sincosf(th, &sn, &cs);
                    float z0 = rr * cs, z1 = rr * sn;
                    float rr2 = rr * rr;
                    float sumT = 0.0f, sumS = 0.0f;
#pragma unroll
                    for (int hf = 0; hf < 2; hf++) {
                        int nj = 2 * dj + hf;
                        float p0 = acc[mi][nj][rsel * 2 + 0] + bb2[nj][0];
                        float p1 = acc[mi][nj][rsel * 2 + 1] + bb2[nj][1];
                        float nrm = sqrtf(p0 * p0 + p1 * p1);
                        float f = rr * 0.99f / (1.0f + nrm);
                        float w0 = f * p0, w1 = f * p1;
                        float zw0 = z0 - w0, zw1 = z1 - w1;
                        float dist2 = zw0 * zw0 + zw1 * zw1;
                        float scale = (rr2 - (w0 * w0 + w1 * w1)) / dist2;
                        float zo0 = scale * zw0 - w0;
                        float zo1 = scale * zw1 - w1;
                        float ang = atan2f(zo1, zo0);
                        if (ang < 0.0f) ang += TWO_PI_F;
                        sumT += ang;
                        sumS += scale;
                    }
                    sumT += __shfl_xor_sync(0xffffffffu, sumT, 1);
                    sumS += __shfl_xor_sync(0xffffffffu, sumS, 1);
                    sumT += __shfl_xor_sync(0xffffffffu, sumT, 2);
                    sumS += __shfl_xor_sync(0xffffffffu, sumS, 2);
                    if (tig == 0) {
                        out[grow * DH + d] = sumT * 0.125f;
                        out[(size_t)B_TOTAL * DH + grow * DH + d] =
                            logf(sumS * 0.125f + 1e-8f);
                    }
                }
            }
    }
}

// ---------------- launch ----------------
extern "C" void kernel_launch(void* const* d_in, const int* in_sizes, int n_in,
                              void* d_out, int out_size) {
    const float* theta = (const float*)d_in[0];
    const float* r     = (const float*)d_in[1];
    const float* x     = (const float*)d_in[2];
    const float* W1    = (const float*)d_in[3];
    const float* b1    = (const float*)d_in[4];
    const float* W2    = (const float*)d_in[5];
    const float* b2    = (const float*)d_in[6];
    const float* eta   = (const float*)d_in[7];
    float* out = (float*)d_out;

    pack_x_kernel<<<(B_TOTAL * 64) / 256, 256>>>(x);
    pack_w1_kernel<<<(512 * 64) / 256, 256>>>(W1);
    pack_w2_kernel<<<(512 * 512) / 256, 256>>>(W2, eta);

    const int smem_bytes = 4 * 49152;   // 192 KB, 4-stage pipeline
    cudaFuncSetAttribute(mma_gemm_kernel<64, true>,
                         cudaFuncAttributeMaxDynamicSharedMemorySize, smem_bytes);
    cudaFuncSetAttribute(mma_gemm_kernel<512, false>,
                         cudaFuncAttributeMaxDynamicSharedMemorySize, smem_bytes);

    dim3 grid(2, B_TOTAL / 128);   // n-half fast => row-sharing CTAs L2-adjacent
    mma_gemm_kernel<64, true><<<grid, 256, smem_bytes>>>(
        b1, nullptr, nullptr, nullptr, nullptr);
    mma_gemm_kernel<512, false><<<grid, 256, smem_bytes>>>(
        b2, theta, r, eta, out);
}

// round 8
// speedup vs baseline: 2.2062x; 1.4204x over previous
#include <cuda_runtime.h>
#include <cuda_fp16.h>
#include <math.h>
#include <stdint.h>

// ---------------- problem constants ----------------
#define B_TOTAL   131072
#define DH        32
#define TWO_PI_F  6.283185307179586f

// ---------------- device scratch (static, no alloc) ----------------
__device__ __half g_xhi[(size_t)B_TOTAL * 64];
__device__ __half g_xlo[(size_t)B_TOTAL * 64];
__device__ __half g_hhi[(size_t)B_TOTAL * 512];
__device__ __half g_hlo[(size_t)B_TOTAL * 512];
__device__ __half g_w1hi[512 * 64];    // W1^T [n=512][k=64]
__device__ __half g_w1lo[512 * 64];
__device__ __half g_w2hi[512 * 512];   // (W2*eta)^T [n=512][k=512]
__device__ __half g_w2lo[512 * 512];

__device__ __forceinline__ void split_h(float v, __half& hi, __half& lo) {
    hi = __float2half_rn(v);
    lo = __float2half_rn(v - __half2float(hi));
}

// ---------------- pack kernels ----------------
__global__ void pack_x_kernel(const float* __restrict__ x) {
    size_t i = (size_t)blockIdx.x * blockDim.x + threadIdx.x;  // B*64
    __half hi, lo;
    split_h(x[i], hi, lo);
    g_xhi[i] = hi;
    g_xlo[i] = lo;
}
__global__ void pack_w1_kernel(const float* __restrict__ W1) {
    int i = blockIdx.x * blockDim.x + threadIdx.x;   // 512*64
    int n = i >> 6, k = i & 63;
    __half hi, lo;
    split_h(W1[k * 512 + n], hi, lo);
    g_w1hi[i] = hi;    // [n][k] layout, i = n*64+k
    g_w1lo[i] = lo;
}
__global__ void pack_w2_kernel(const float* __restrict__ W2,
                               const float* __restrict__ eta) {
    int i = blockIdx.x * blockDim.x + threadIdx.x;   // 512*512
    int n = i >> 9, k = i & 511;
    __half hi, lo;
    split_h(W2[k * 513 + n] * eta[0], hi, lo);
    g_w2hi[i] = hi;    // [n][k], i = n*512+k
    g_w2lo[i] = lo;
}

// ---------------------------------------------------------------------------
// fp16x3-split GEMM via mma.sync m16n8k16 (row.col, fp32 accum).
// CTA: 512 threads (16 warps -> 4 warps/SMSP), output tile M=128 x N=256.
// Warp grid 4(m) x 4(n): warp tile 32x64 -> acc[2 mi][8 nj][4] fp32 (64 regs).
// K' = 3*KSEG as segments: A' = [Ahi|Ahi|Alo], B' = [Bhi|Blo|Bhi].
// Staging: k64 chunks, A 16KB + B 32KB, 4-stage cp.async pipeline (192KB),
// 16B-XOR swizzle for conflict-free ldmatrix.
// Grid: (2 n-halves, B/128 row-tiles) so row-sharing CTAs are L2-adjacent.
// PHASE1: A=x splits, B=W1^T splits, epilogue relu+split -> g_h{hi,lo}
// PHASE2: A=h splits, B=(W2*eta)^T splits, epilogue Moebius -> out
// ---------------------------------------------------------------------------
template <int KSEG, bool PHASE1>
__global__ __launch_bounds__(512, 1)
void mma_gemm_kernel(const float* __restrict__ bias,
                     const float* __restrict__ theta,
                     const float* __restrict__ r_in,
                     const float* __restrict__ eta,
                     float* __restrict__ out) {
    constexpr int CPS = KSEG / 64;      // chunks per segment
    constexpr int NC = 3 * CPS;         // total chunks
    constexpr int SSTRIDE = KSEG * 2;   // source row stride (bytes)
    constexpr int STAGES = 4;

    extern __shared__ char smem[];
    const uint32_t sbase = (uint32_t)__cvta_generic_to_shared(smem);

    const int tid = threadIdx.x;
    const int lane = tid & 31;
    const int wid = tid >> 5;
    const int wm = (wid & 3) * 32;       // warp M offset within CTA tile
    const int wn = (wid >> 2) * 64;      // warp N offset within CTA tile
    const int blockRow = blockIdx.y * 128;
    const int colbase = blockIdx.x * 256;

    const __half* Ahi = PHASE1 ? g_xhi : g_hhi;
    const __half* Alo = PHASE1 ? g_xlo : g_hlo;
    const __half* Bhi = PHASE1 ? g_w1hi : g_w2hi;
    const __half* Blo = PHASE1 ? g_w1lo : g_w2lo;

    float acc[2][8][4];
#pragma unroll
    for (int mi = 0; mi < 2; mi++)
#pragma unroll
        for (int nj = 0; nj < 8; nj++)
#pragma unroll
            for (int q = 0; q < 4; q++) acc[mi][nj][q] = 0.0f;

    // ldmatrix lane-address components.
    // A (m16 x k16 per x4): lane bit3 -> +8 rows, bit4 -> +8 k-halves.
    const int aRow = wm + (lane & 7) + ((lane >> 3) & 1) * 8;
    const int aU = (lane >> 4) & 1;
    const int aX = aRow & 7;
    // B (two n8 x k16 per x4): bit4 -> +8 n-rows, bit3 -> +8 k-halves.
    const int bRow = wn + (lane & 7) + ((lane >> 4) & 1) * 8;
    const int bU = (lane >> 3) & 1;
    const int bX = bRow & 7;

    auto loadc = [&](int c) {
        int seg = c / CPS;
        int kc = c - seg * CPS;
        const char* ag = (const char*)(seg == 2 ? Alo : Ahi) +
                         (size_t)blockRow * SSTRIDE + (size_t)kc * 128;
        const char* bg = (const char*)(seg == 1 ? Blo : Bhi) +
                         (size_t)colbase * SSTRIDE + (size_t)kc * 128;
        uint32_t ab = sbase + (uint32_t)(c % STAGES) * 49152u;
        uint32_t bb = ab + 16384u;
#pragma unroll
        for (int j = 0; j < 2; j++) {                 // A: 1024 x 16B units
            int gi = tid + 512 * j;
            int row = gi >> 3, u = gi & 7;
            const char* src = ag + (size_t)row * SSTRIDE + u * 16;
            uint32_t dst = ab + row * 128u + (uint32_t)((u ^ (row & 7)) << 4);
            asm volatile("cp.async.cg.shared.global [%0], [%1], 16;"
                         :: "r"(dst), "l"(src));
        }
#pragma unroll
        for (int j = 0; j < 4; j++) {                 // B: 2048 x 16B units
            int gi = tid + 512 * j;
            int row = gi >> 3, u = gi & 7;
            const char* src = bg + (size_t)row * SSTRIDE + u * 16;
            uint32_t dst = bb + row * 128u + (uint32_t)((u ^ (row & 7)) << 4);
            asm volatile("cp.async.cg.shared.global [%0], [%1], 16;"
                         :: "r"(dst), "l"(src));
        }
        asm volatile("cp.async.commit_group;");
    };

    // ---- prologue: fill STAGES-1 buffers (empty groups keep FIFO uniform) ----
#pragma unroll
    for (int s = 0; s < STAGES - 1; s++) {
        if (s < NC) loadc(s);
        else asm volatile("cp.async.commit_group;");
    }
    asm volatile("cp.async.wait_group %0;" :: "n"(STAGES - 2));
    __syncthreads();   // chunk 0 visible

#pragma unroll 1
    for (int c = 0; c < NC; c++) {
        // refill buffer (c-1)%STAGES — its readers passed last iter's barrier
        if (c + STAGES - 1 < NC) loadc(c + STAGES - 1);
        else asm volatile("cp.async.commit_group;");

        uint32_t ab = sbase + (uint32_t)(c % STAGES) * 49152u;
        uint32_t bb = ab + 16384u;
#pragma unroll
        for (int kk = 0; kk < 4; kk++) {
            uint32_t a[2][4];
#pragma unroll
            for (int mi = 0; mi < 2; mi++) {
                int row = aRow + mi * 16;
                uint32_t addr = ab + row * 128u +
                                (uint32_t)(((kk * 2 + aU) ^ aX) << 4);
                asm volatile(
                    "ldmatrix.sync.aligned.m8n8.x4.shared.b16 {%0,%1,%2,%3}, [%4];"
                    : "=r"(a[mi][0]), "=r"(a[mi][1]), "=r"(a[mi][2]), "=r"(a[mi][3])
                    : "r"(addr));
            }
            uint32_t b[8][2];
#pragma unroll
            for (int p = 0; p < 4; p++) {
                int row = bRow + p * 16;
                uint32_t addr = bb + row * 128u +
                                (uint32_t)(((kk * 2 + bU) ^ bX) << 4);
                asm volatile(
                    "ldmatrix.sync.aligned.m8n8.x4.shared.b16 {%0,%1,%2,%3}, [%4];"
                    : "=r"(b[2 * p][0]), "=r"(b[2 * p][1]),
                      "=r"(b[2 * p + 1][0]), "=r"(b[2 * p + 1][1])
                    : "r"(addr));
            }
#pragma unroll
            for (int mi = 0; mi < 2; mi++)
#pragma unroll
                for (int nj = 0; nj < 8; nj++) {
                    asm volatile(
                        "mma.sync.aligned.m16n8k16.row.col.f32.f16.f16.f32 "
                        "{%0,%1,%2,%3}, {%4,%5,%6,%7}, {%8,%9}, {%0,%1,%2,%3};"
                        : "+f"(acc[mi][nj][0]), "+f"(acc[mi][nj][1]),
                          "+f"(acc[mi][nj][2]), "+f"(acc[mi][nj][3])
                        : "r"(a[mi][0]), "r"(a[mi][1]), "r"(a[mi][2]), "r"(a[mi][3]),
                          "r"(b[nj][0]), "r"(b[nj][1]));
                }
        }
        // chunk c+1 complete (pending <= STAGES-2 groups), readers re-synced
        asm volatile("cp.async.wait_group %0;" :: "n"(STAGES - 2));
        __syncthreads();
    }

    // ---- epilogue ----
    const int g = lane >> 2;       // row within m16 half
    const int tig = lane & 3;      // col pair within n8

    if constexpr (PHASE1) {
#pragma unroll
        for (int mi = 0; mi < 2; mi++)
#pragma unroll
            for (int rsel = 0; rsel < 2; rsel++) {
                int grow = blockRow + wm + mi * 16 + g + rsel * 8;
#pragma unroll
                for (int nj = 0; nj < 8; nj++) {
                    int cc = colbase + wn + nj * 8 + 2 * tig;
                    float h0 = fmaxf(acc[mi][nj][rsel * 2 + 0] + bias[cc], 0.0f);
                    float h1 = fmaxf(acc[mi][nj][rsel * 2 + 1] + bias[cc + 1], 0.0f);
                    __half hi0, lo0, hi1, lo1;
                    split_h(h0, hi0, lo0);
                    split_h(h1, hi1, lo1);
                    *reinterpret_cast<__half2*>(&g_hhi[(size_t)grow * 512 + cc]) =
                        __halves2half2(hi0, hi1);
                    *reinterpret_cast<__half2*>(&g_hlo[(size_t)grow * 512 + cc]) =
                        __halves2half2(lo0, lo1);
                }
            }
    } else {
        const float e = eta[0];
        float bb2[8][2];
#pragma unroll
        for (int nj = 0; nj < 8; nj++) {
            int cc = colbase + wn + nj * 8 + 2 * tig;
            bb2[nj][0] = bias[cc] * e;
            bb2[nj][1] = bias[cc + 1] * e;
        }
        const int dbase = (colbase + wn) >> 4;

#pragma unroll
        for (int mi = 0; mi < 2; mi++)
#pragma unroll
            for (int rsel = 0; rsel < 2; rsel++) {
                int grow = blockRow + wm + mi * 16 + g + rsel * 8;
#pragma unroll
                for (int dj = 0; dj < 4; dj++) {
                    int d = dbase + dj;
                    float th = theta[grow * DH + d];
                    float rr = r_in[grow * DH + d];
                    float sn, cs;
                    sincosf(th, &sn, &cs);
                    float z0 = rr * cs, z1 = rr * sn;
                    float rr2 = rr * rr;
                    float sumT = 0.0f, sumS = 0.0f;
#pragma unroll
                    for (int hf = 0; hf < 2; hf++) {
                        int nj = 2 * dj + hf;
                        float p0 = acc[mi][nj][rsel * 2 + 0] + bb2[nj][0];
                        float p1 = acc[mi][nj][rsel * 2 + 1] + bb2[nj][1];
                        float nrm = sqrtf(p0 * p0 + p1 * p1);
                        float f = rr * 0.99f / (1.0f + nrm);
                        float w0 = f * p0, w1 = f * p1;
                        float zw0 = z0 - w0, zw1 = z1 - w1;
                        float dist2 = zw0 * zw0 + zw1 * zw1;
                        float scale = (rr2 - (w0 * w0 + w1 * w1)) / dist2;
                        float zo0 = scale * zw0 - w0;
                        float zo1 = scale * zw1 - w1;
                        float ang = atan2f(zo1, zo0);
                        if (ang < 0.0f) ang += TWO_PI_F;
                        sumT += ang;
                        sumS += scale;
                    }
                    sumT += __shfl_xor_sync(0xffffffffu, sumT, 1);
                    sumS += __shfl_xor_sync(0xffffffffu, sumS, 1);
                    sumT += __shfl_xor_sync(0xffffffffu, sumT, 2);
                    sumS += __shfl_xor_sync(0xffffffffu, sumS, 2);
                    if (tig == 0) {
                        out[grow * DH + d] = sumT * 0.125f;
                        out[(size_t)B_TOTAL * DH + grow * DH + d] =
                            logf(sumS * 0.125f + 1e-8f);
                    }
                }
            }
    }
}

// ---------------- launch ----------------
extern "C" void kernel_launch(void* const* d_in, const int* in_sizes, int n_in,
                              void* d_out, int out_size) {
    const float* theta = (const float*)d_in[0];
    const float* r     = (const float*)d_in[1];
    const float* x     = (const float*)d_in[2];
    const float* W1    = (const float*)d_in[3];
    const float* b1    = (const float*)d_in[4];
    const float* W2    = (const float*)d_in[5];
    const float* b2    = (const float*)d_in[6];
    const float* eta   = (const float*)d_in[7];
    float* out = (float*)d_out;

    pack_x_kernel<<<(B_TOTAL * 64) / 256, 256>>>(x);
    pack_w1_kernel<<<(512 * 64) / 256, 256>>>(W1);
    pack_w2_kernel<<<(512 * 512) / 256, 256>>>(W2, eta);

    const int smem_bytes = 4 * 49152;   // 192 KB, 4-stage pipeline
    cudaFuncSetAttribute(mma_gemm_kernel<64, true>,
                         cudaFuncAttributeMaxDynamicSharedMemorySize, smem_bytes);
    cudaFuncSetAttribute(mma_gemm_kernel<512, false>,
                         cudaFuncAttributeMaxDynamicSharedMemorySize, smem_bytes);

    dim3 grid(2, B_TOTAL / 128);   // n-half fast => row-sharing CTAs L2-adjacent
    mma_gemm_kernel<64, true><<<grid, 512, smem_bytes>>>(
        b1, nullptr, nullptr, nullptr, nullptr);
    mma_gemm_kernel<512, false><<<grid, 512, smem_bytes>>>(
        b2, theta, r, eta, out);
}

// round 9
// speedup vs baseline: 2.5246x; 1.1443x over previous
#include <cuda_runtime.h>
#include <cuda_fp16.h>
#include <math.h>
#include <stdint.h>

// ---------------- problem constants ----------------
#define B_TOTAL   131072
#define DH        32
#define TWO_PI_F  6.283185307179586f

// ---------------- device scratch (static, no alloc) ----------------
__device__ __half g_xhi[(size_t)B_TOTAL * 64];
__device__ __half g_xlo[(size_t)B_TOTAL * 64];
__device__ __half g_hhi[(size_t)B_TOTAL * 512];
__device__ __half g_hlo[(size_t)B_TOTAL * 512];
__device__ __half g_w1hi[512 * 64];    // W1^T [n=512][k=64]
__device__ __half g_w1lo[512 * 64];
__device__ __half g_w2hi[512 * 512];   // (W2*eta)^T [n=512][k=512]
__device__ __half g_w2lo[512 * 512];

__device__ __forceinline__ void split_h(float v, __half& hi, __half& lo) {
    hi = __float2half_rn(v);
    lo = __float2half_rn(v - __half2float(hi));
}

// ---------------- pack kernels ----------------
__global__ void pack_x_kernel(const float* __restrict__ x) {
    size_t i = (size_t)blockIdx.x * blockDim.x + threadIdx.x;  // B*64
    __half hi, lo;
    split_h(x[i], hi, lo);
    g_xhi[i] = hi;
    g_xlo[i] = lo;
}
__global__ void pack_w1_kernel(const float* __restrict__ W1) {
    int i = blockIdx.x * blockDim.x + threadIdx.x;   // 512*64
    int n = i >> 6, k = i & 63;
    __half hi, lo;
    split_h(W1[k * 512 + n], hi, lo);
    g_w1hi[i] = hi;    // [n][k] layout, i = n*64+k
    g_w1lo[i] = lo;
}
__global__ void pack_w2_kernel(const float* __restrict__ W2,
                               const float* __restrict__ eta) {
    int i = blockIdx.x * blockDim.x + threadIdx.x;   // 512*512
    int n = i >> 9, k = i & 511;
    __half hi, lo;
    split_h(W2[k * 513 + n] * eta[0], hi, lo);
    g_w2hi[i] = hi;    // [n][k], i = n*512+k
    g_w2lo[i] = lo;
}

// ---------------------------------------------------------------------------
// fp16x3-split GEMM via mma.sync m16n8k16 (row.col, fp32 accum).
// CTA: 256 threads (8 warps), 2 CTAs/SM (independent pipelines hide barrier
// lockstep). Output tile M=128 x N=128; warp grid 4(m) x 2(n), warp tile
// 32x64 -> acc[2 mi][8 nj][4] fp32 (64 regs).
// K' = 3*KSEG as segments: A' = [Ahi|Ahi|Alo], B' = [Bhi|Blo|Bhi].
// Staging: k64 chunks, A 16KB + B 16KB, 3-stage cp.async pipeline (96KB/CTA),
// 16B-XOR swizzle for conflict-free ldmatrix.
// Grid: (4 n-quarters, B/128 row-tiles), x fastest -> row-sharing CTAs
// schedule-adjacent (A/h reads L2-hot).
// PHASE1: A=x splits, B=W1^T splits, epilogue relu+split -> g_h{hi,lo}
// PHASE2: A=h splits, B=(W2*eta)^T splits, epilogue Moebius -> out
// ---------------------------------------------------------------------------
template <int KSEG, bool PHASE1>
__global__ __launch_bounds__(256, 2)
void mma_gemm_kernel(const float* __restrict__ bias,
                     const float* __restrict__ theta,
                     const float* __restrict__ r_in,
                     const float* __restrict__ eta,
                     float* __restrict__ out) {
    constexpr int CPS = KSEG / 64;      // chunks per segment
    constexpr int NC = 3 * CPS;         // total chunks
    constexpr int SSTRIDE = KSEG * 2;   // source row stride (bytes)
    constexpr int STAGES = 3;
    constexpr int CHUNK_BYTES = 32768;  // A 16KB + B 16KB

    extern __shared__ char smem[];
    const uint32_t sbase = (uint32_t)__cvta_generic_to_shared(smem);

    const int tid = threadIdx.x;
    const int lane = tid & 31;
    const int wid = tid >> 5;
    const int wm = (wid & 3) * 32;       // warp M offset within CTA tile
    const int wn = (wid >> 2) * 64;      // warp N offset within CTA tile
    const int blockRow = blockIdx.y * 128;
    const int colbase = blockIdx.x * 128;

    const __half* Ahi = PHASE1 ? g_xhi : g_hhi;
    const __half* Alo = PHASE1 ? g_xlo : g_hlo;
    const __half* Bhi = PHASE1 ? g_w1hi : g_w2hi;
    const __half* Blo = PHASE1 ? g_w1lo : g_w2lo;

    float acc[2][8][4];
#pragma unroll
    for (int mi = 0; mi < 2; mi++)
#pragma unroll
        for (int nj = 0; nj < 8; nj++)
#pragma unroll
            for (int q = 0; q < 4; q++) acc[mi][nj][q] = 0.0f;

    // ldmatrix lane-address components.
    // A (m16 x k16 per x4): lane bit3 -> +8 rows, bit4 -> +8 k-halves.
    const int aRow = wm + (lane & 7) + ((lane >> 3) & 1) * 8;
    const int aU = (lane >> 4) & 1;
    const int aX = aRow & 7;
    // B (two n8 x k16 per x4): bit4 -> +8 n-rows, bit3 -> +8 k-halves.
    const int bRow = wn + (lane & 7) + ((lane >> 4) & 1) * 8;
    const int bU = (lane >> 3) & 1;
    const int bX = bRow & 7;

    auto loadc = [&](int c) {
        int seg = c / CPS;
        int kc = c - seg * CPS;
        const char* ag = (const char*)(seg == 2 ? Alo : Ahi) +
                         (size_t)blockRow * SSTRIDE + (size_t)kc * 128;
        const char* bg = (const char*)(seg == 1 ? Blo : Bhi) +
                         (size_t)colbase * SSTRIDE + (size_t)kc * 128;
        uint32_t ab = sbase + (uint32_t)(c % STAGES) * CHUNK_BYTES;
        uint32_t bb = ab + 16384u;
#pragma unroll
        for (int j = 0; j < 4; j++) {                 // A: 1024 x 16B units
            int gi = tid + 256 * j;
            int row = gi >> 3, u = gi & 7;
            const char* src = ag + (size_t)row * SSTRIDE + u * 16;
            uint32_t dst = ab + row * 128u + (uint32_t)((u ^ (row & 7)) << 4);
            asm volatile("cp.async.cg.shared.global [%0], [%1], 16;"
                         :: "r"(dst), "l"(src));
        }
#pragma unroll
        for (int j = 0; j < 4; j++) {                 // B: 1024 x 16B units
            int gi = tid + 256 * j;
            int row = gi >> 3, u = gi & 7;
            const char* src = bg + (size_t)row * SSTRIDE + u * 16;
            uint32_t dst = bb + row * 128u + (uint32_t)((u ^ (row & 7)) << 4);
            asm volatile("cp.async.cg.shared.global [%0], [%1], 16;"
                         :: "r"(dst), "l"(src));
        }
        asm volatile("cp.async.commit_group;");
    };

    // ---- prologue: fill STAGES-1 buffers (empty groups keep FIFO uniform) ----
#pragma unroll
    for (int s = 0; s < STAGES - 1; s++) {
        if (s < NC) loadc(s);
        else asm volatile("cp.async.commit_group;");
    }
    asm volatile("cp.async.wait_group %0;" :: "n"(STAGES - 2));
    __syncthreads();   // chunk 0 visible

#pragma unroll 1
    for (int c = 0; c < NC; c++) {
        // refill buffer (c-1)%STAGES — its readers passed last iter's barrier
        if (c + STAGES - 1 < NC) loadc(c + STAGES - 1);
        else asm volatile("cp.async.commit_group;");

        uint32_t ab = sbase + (uint32_t)(c % STAGES) * CHUNK_BYTES;
        uint32_t bb = ab + 16384u;
#pragma unroll
        for (int kk = 0; kk < 4; kk++) {
            uint32_t a[2][4];
#pragma unroll
            for (int mi = 0; mi < 2; mi++) {
                int row = aRow + mi * 16;
                uint32_t addr = ab + row * 128u +
                                (uint32_t)(((kk * 2 + aU) ^ aX) << 4);
                asm volatile(
                    "ldmatrix.sync.aligned.m8n8.x4.shared.b16 {%0,%1,%2,%3}, [%4];"
                    : "=r"(a[mi][0]), "=r"(a[mi][1]), "=r"(a[mi][2]), "=r"(a[mi][3])
                    : "r"(addr));
            }
            uint32_t b[8][2];
#pragma unroll
            for (int p = 0; p < 4; p++) {
                int row = bRow + p * 16;
                uint32_t addr = bb + row * 128u +
                                (uint32_t)(((kk * 2 + bU) ^ bX) << 4);
                asm volatile(
                    "ldmatrix.sync.aligned.m8n8.x4.shared.b16 {%0,%1,%2,%3}, [%4];"
                    : "=r"(b[2 * p][0]), "=r"(b[2 * p][1]),
                      "=r"(b[2 * p + 1][0]), "=r"(b[2 * p + 1][1])
                    : "r"(addr));
            }
#pragma unroll
            for (int mi = 0; mi < 2; mi++)
#pragma unroll
                for (int nj = 0; nj < 8; nj++) {
                    asm volatile(
                        "mma.sync.aligned.m16n8k16.row.col.f32.f16.f16.f32 "
                        "{%0,%1,%2,%3}, {%4,%5,%6,%7}, {%8,%9}, {%0,%1,%2,%3};"
                        : "+f"(acc[mi][nj][0]), "+f"(acc[mi][nj][1]),
                          "+f"(acc[mi][nj][2]), "+f"(acc[mi][nj][3])
                        : "r"(a[mi][0]), "r"(a[mi][1]), "r"(a[mi][2]), "r"(a[mi][3]),
                          "r"(b[nj][0]), "r"(b[nj][1]));
                }
        }
        // chunk c+1 complete (pending <= STAGES-2 groups), readers re-synced
        asm volatile("cp.async.wait_group %0;" :: "n"(STAGES - 2));
        __syncthreads();
    }

    // ---- epilogue ----
    const int g = lane >> 2;       // row within m16 half
    const int tig = lane & 3;      // col pair within n8

    if constexpr (PHASE1) {
#pragma unroll
        for (int mi = 0; mi < 2; mi++)
#pragma unroll
            for (int rsel = 0; rsel < 2; rsel++) {
                int grow = blockRow + wm + mi * 16 + g + rsel * 8;
#pragma unroll
                for (int nj = 0; nj < 8; nj++) {
                    int cc = colbase + wn + nj * 8 + 2 * tig;
                    float h0 = fmaxf(acc[mi][nj][rsel * 2 + 0] + bias[cc], 0.0f);
                    float h1 = fmaxf(acc[mi][nj][rsel * 2 + 1] + bias[cc + 1], 0.0f);
                    __half hi0, lo0, hi1, lo1;
                    split_h(h0, hi0, lo0);
                    split_h(h1, hi1, lo1);
                    *reinterpret_cast<__half2*>(&g_hhi[(size_t)grow * 512 + cc]) =
                        __halves2half2(hi0, hi1);
                    *reinterpret_cast<__half2*>(&g_hlo[(size_t)grow * 512 + cc]) =
                        __halves2half2(lo0, lo1);
                }
            }
    } else {
        const float e = eta[0];
        float bb2[8][2];
#pragma unroll
        for (int nj = 0; nj < 8; nj++) {
            int cc = colbase + wn + nj * 8 + 2 * tig;
            bb2[nj][0] = bias[cc] * e;
            bb2[nj][1] = bias[cc + 1] * e;
        }
        const int dbase = (colbase + wn) >> 4;

#pragma unroll
        for (int mi = 0; mi < 2; mi++)
#pragma unroll
            for (int rsel = 0; rsel < 2; rsel++) {
                int grow = blockRow + wm + mi * 16 + g + rsel * 8;
#pragma unroll
                for (int dj = 0; dj < 4; dj++) {
                    int d = dbase + dj;
                    float th = theta[grow * DH + d];
                    float rr = r_in[grow * DH + d];
                    float sn, cs;
                    sincosf(th, &sn, &cs);
                    float z0 = rr * cs, z1 = rr * sn;
                    float rr2 = rr * rr;
                    float sumT = 0.0f, sumS = 0.0f;
#pragma unroll
                    for (int hf = 0; hf < 2; hf++) {
                        int nj = 2 * dj + hf;
                        float p0 = acc[mi][nj][rsel * 2 + 0] + bb2[nj][0];
                        float p1 = acc[mi][nj][rsel * 2 + 1] + bb2[nj][1];
                        float nrm = sqrtf(p0 * p0 + p1 * p1);
                        float f = rr * 0.99f / (1.0f + nrm);
                        float w0 = f * p0, w1 = f * p1;
                        float zw0 = z0 - w0, zw1 = z1 - w1;
                        float dist2 = zw0 * zw0 + zw1 * zw1;
                        float scale = (rr2 - (w0 * w0 + w1 * w1)) / dist2;
                        float zo0 = scale * zw0 - w0;
                        float zo1 = scale * zw1 - w1;
                        float ang = atan2f(zo1, zo0);
                        if (ang < 0.0f) ang += TWO_PI_F;
                        sumT += ang;
                        sumS += scale;
                    }
                    sumT += __shfl_xor_sync(0xffffffffu, sumT, 1);
                    sumS += __shfl_xor_sync(0xffffffffu, sumS, 1);
                    sumT += __shfl_xor_sync(0xffffffffu, sumT, 2);
                    sumS += __shfl_xor_sync(0xffffffffu, sumS, 2);
                    if (tig == 0) {
                        out[grow * DH + d] = sumT * 0.125f;
                        out[(size_t)B_TOTAL * DH + grow * DH + d] =
                            logf(sumS * 0.125f + 1e-8f);
                    }
                }
            }
    }
}

// ---------------- launch ----------------
extern "C" void kernel_launch(void* const* d_in, const int* in_sizes, int n_in,
                              void* d_out, int out_size) {
    const float* theta = (const float*)d_in[0];
    const float* r     = (const float*)d_in[1];
    const float* x     = (const float*)d_in[2];
    const float* W1    = (const float*)d_in[3];
    const float* b1    = (const float*)d_in[4];
    const float* W2    = (const float*)d_in[5];
    const float* b2    = (const float*)d_in[6];
    const float* eta   = (const float*)d_in[7];
    float* out = (float*)d_out;

    pack_x_kernel<<<(B_TOTAL * 64) / 256, 256>>>(x);
    pack_w1_kernel<<<(512 * 64) / 256, 256>>>(W1);
    pack_w2_kernel<<<(512 * 512) / 256, 256>>>(W2, eta);

    const int smem_bytes = 3 * 32768;   // 96 KB, 3-stage pipeline, 2 CTAs/SM
    cudaFuncSetAttribute(mma_gemm_kernel<64, true>,
                         cudaFuncAttributeMaxDynamicSharedMemorySize, smem_bytes);
    cudaFuncSetAttribute(mma_gemm_kernel<512, false>,
                         cudaFuncAttributeMaxDynamicSharedMemorySize, smem_bytes);

    dim3 grid(4, B_TOTAL / 128);   // n-quarter fast => row-sharing CTAs adjacent
    mma_gemm_kernel<64, true><<<grid, 256, smem_bytes>>>(
        b1, nullptr, nullptr, nullptr, nullptr);
    mma_gemm_kernel<512, false><<<grid, 256, smem_bytes>>>(
        b2, theta, r, eta, out);
}